// round 9
// baseline (speedup 1.0000x reference)
#include <cuda_runtime.h>

#define SEQ   512
#define BATCH 4096
#define HID   30
#define ROWF  40   // floats per buf row: 32 loaded (30 h + 2 zero pad) + 8 pad
#define PF    8    // X prefetch depth

typedef unsigned long long ull;

__device__ __forceinline__ ull pk2(float a, float b) {
    ull r; asm("mov.b64 %0,{%1,%2};" : "=l"(r) : "f"(a), "f"(b)); return r;
}
__device__ __forceinline__ void unpk2(ull v, float& a, float& b) {
    asm("mov.b64 {%0,%1},%2;" : "=f"(a), "=f"(b) : "l"(v));
}
// Packed dual-fp32 FMA / ADD (Blackwell f32x2).
__device__ __forceinline__ ull ffma2(ull a, ull b, ull c) {
    ull d; asm("fma.rn.f32x2 %0,%1,%2,%3;" : "=l"(d) : "l"(a), "l"(b), "l"(c)); return d;
}
__device__ __forceinline__ ull add2(ull a, ull b) {
    ull d; asm("add.rn.f32x2 %0,%1,%2;" : "=l"(d) : "l"(a), "l"(b)); return d;
}

// tanh with PRE-SCALED input (2*log2e folded into weights): tanh = 1 - 2/(exp2(v)+1).
__device__ __forceinline__ float tanh_ps(float v) {
    float e, r;
    asm("ex2.approx.f32 %0, %1;" : "=f"(e) : "f"(v));
    asm("rcp.approx.f32 %0, %1;" : "=f"(r) : "f"(e + 1.0f));
    return fmaf(-2.0f, r, 1.0f);
}

__global__ void __launch_bounds__(32, 28)
rnn_kernel(const float* __restrict__ X,     const float* __restrict__ W_ih,
           const float* __restrict__ W_hh,  const float* __restrict__ b_ih,
           const float* __restrict__ b_hh,  const float* __restrict__ W_out,
           const float* __restrict__ b_out, float* __restrict__ Y)
{
    // ONE batch per warp. h double buffer, natural layout: hbuf[buf][k] = h[k].
    __shared__ __align__(16) float hbuf[2][ROWF];

    const int lane = threadIdx.x;          // lane j owns hidden unit j (j<30); 30/31 are pad writers
    const int j    = lane;
    const bool act = (j < HID);
    const int batch = blockIdx.x;

    const float SC = 2.8853900817779268f;  // 2*log2(e), folded into pre-tanh weights

    // ---- W_hh row j packed over (k even, k odd): 15 pairs ----
    ull w[15];
#pragma unroll
    for (int i = 0; i < 15; i++) {
        float a = act ? SC * W_hh[j * HID + 2 * i]     : 0.0f;
        float c = act ? SC * W_hh[j * HID + 2 * i + 1] : 0.0f;
        w[i] = pk2(a, c);
    }
    const float wih = act ? SC * W_ih[j] : 0.0f;
    const float bi  = act ? SC * (b_ih[j] + b_hh[j]) : 0.0f;
    const float wo  = act ? W_out[j] : 0.0f;
    const float bo  = b_out[0];

    // ---- zero both buffers incl. pad ----
#pragma unroll
    for (int i = lane; i < 2 * ROWF; i += 32)
        (&hbuf[0][0])[i] = 0.0f;
    __syncwarp();

    const float* Xb = X + batch;
    float*       Yb = Y + batch;

    // ---- deep X prefetch ring (broadcast LDG, 1 line per warp) ----
    float xbuf[PF];
#pragma unroll
    for (int i = 0; i < PF; i++) xbuf[i] = Xb[i * BATCH];

    float pp = 0.0f;                       // y partial, reduced one step late

    for (int s0 = 0; s0 < SEQ; s0 += PF) {
        const float* Xpf = Xb + (s0 + PF) * BATCH;
        const bool more = (s0 + PF) < SEQ;

#pragma unroll
        for (int u = 0; u < PF; u++) {
            const int s = s0 + u;
            const float4* hc = (const float4*)&hbuf[u & 1][0];
            float*        hn = &hbuf[(u & 1) ^ 1][0];

            // ---- previous step's y: 5-level shfl butterfly (pipelined one step late) ----
            float r = pp;
#pragma unroll
            for (int m = 1; m < 32; m <<= 1)
                r += __shfl_xor_sync(0xffffffffu, r, m);
            if (lane == 0 && s > 0) Yb[(s - 1) * BATCH] = r + bo;

            // ---- consume x, refill slot PF steps ahead ----
            const float xc = xbuf[u];
            if (more) xbuf[u] = Xpf[u * BATCH];

            // ---- matvec row j: 15 k-pairs, 4 split chains ----
            // (8 broadcast LDS.128; pairs 0..14 = k 0..29; pad k30/31 unused)
            const float4 f0 = hc[0], f1 = hc[1], f2 = hc[2], f3 = hc[3];
            const float4 f4 = hc[4], f5 = hc[5], f6 = hc[6], f7 = hc[7];
            ull a0 = pk2(bi, 0.0f), a1 = 0ull, a2 = 0ull, a3 = 0ull;
            a0 = ffma2(w[0],  pk2(f0.x, f0.y), a0);
            a1 = ffma2(w[1],  pk2(f0.z, f0.w), a1);
            a2 = ffma2(w[2],  pk2(f1.x, f1.y), a2);
            a3 = ffma2(w[3],  pk2(f1.z, f1.w), a3);
            a0 = ffma2(w[4],  pk2(f2.x, f2.y), a0);
            a1 = ffma2(w[5],  pk2(f2.z, f2.w), a1);
            a2 = ffma2(w[6],  pk2(f3.x, f3.y), a2);
            a3 = ffma2(w[7],  pk2(f3.z, f3.w), a3);
            a0 = ffma2(w[8],  pk2(f4.x, f4.y), a0);
            a1 = ffma2(w[9],  pk2(f4.z, f4.w), a1);
            a2 = ffma2(w[10], pk2(f5.x, f5.y), a2);
            a3 = ffma2(w[11], pk2(f5.z, f5.w), a3);
            a0 = ffma2(w[12], pk2(f6.x, f6.y), a0);
            a1 = ffma2(w[13], pk2(f6.z, f6.w), a1);
            a2 = ffma2(w[14], pk2(f7.x, f7.y), a2);

            const ull sum = add2(add2(a0, a1), add2(a2, a3));
            float v0, v1;
            unpk2(sum, v0, v1);
            const float v = fmaf(wih, xc, v0 + v1);

            // ---- tanh (pre-scaled); lanes 30/31 produce exact 0 ----
            const float h = tanh_ps(v);

            // ---- publish h_{s+1}: single STS.32, conflict-free ----
            hn[j] = h;

            // ---- this step's y partial ----
            pp = h * wo;

            __syncwarp();
        }
    }

    // final step's y
    {
        float r = pp;
#pragma unroll
        for (int m = 1; m < 32; m <<= 1)
            r += __shfl_xor_sync(0xffffffffu, r, m);
        if (lane == 0) Yb[(SEQ - 1) * BATCH] = r + bo;
    }
}

extern "C" void kernel_launch(void* const* d_in, const int* in_sizes, int n_in,
                              void* d_out, int out_size)
{
    (void)in_sizes; (void)n_in; (void)out_size;
    rnn_kernel<<<BATCH, 32>>>(
        (const float*)d_in[0],  // X
        (const float*)d_in[1],  // W_ih
        (const float*)d_in[2],  // W_hh
        (const float*)d_in[3],  // b_ih
        (const float*)d_in[4],  // b_hh
        (const float*)d_in[5],  // W_out
        (const float*)d_in[6],  // b_out
        (float*)d_out);
}

// round 10
// speedup vs baseline: 1.1041x; 1.1041x over previous
#include <cuda_runtime.h>

#define SEQ   512
#define BATCH 4096
#define HID   30
#define ROWF  40   // floats per (buf,b) row: 32 loaded (30 h + 2 pad) + 8 -> b rows bank-disjoint
#define PF    4    // X prefetch depth (4 x ~380cyc covers DRAM latency; body fits L0 I$)

typedef unsigned long long ull;

__device__ __forceinline__ ull pk2(float a, float b) {
    ull r; asm("mov.b64 %0,{%1,%2};" : "=l"(r) : "f"(a), "f"(b)); return r;
}
__device__ __forceinline__ void unpk2(ull v, float& a, float& b) {
    asm("mov.b64 {%0,%1},%2;" : "=f"(a), "=f"(b) : "l"(v));
}
// Packed dual-fp32 FMA / ADD (Blackwell f32x2).
__device__ __forceinline__ ull ffma2(ull a, ull b, ull c) {
    ull d; asm("fma.rn.f32x2 %0,%1,%2,%3;" : "=l"(d) : "l"(a), "l"(b), "l"(c)); return d;
}
__device__ __forceinline__ ull add2(ull a, ull b) {
    ull d; asm("add.rn.f32x2 %0,%1,%2;" : "=l"(d) : "l"(a), "l"(b)); return d;
}

// tanh with PRE-SCALED input (2*log2e folded into weights): tanh = 1 - 2/(exp2(v)+1).
// tanh_ps(0) == 0 exactly (rcp(2.0) = 0.5 exact).
__device__ __forceinline__ float tanh_ps(float v) {
    float e, r;
    asm("ex2.approx.f32 %0, %1;" : "=f"(e) : "f"(v));
    asm("rcp.approx.f32 %0, %1;" : "=f"(r) : "f"(e + 1.0f));
    return fmaf(-2.0f, r, 1.0f);
}

__global__ void __launch_bounds__(32)
rnn_kernel(const float* __restrict__ X,     const float* __restrict__ W_ih,
           const float* __restrict__ W_hh,  const float* __restrict__ b_ih,
           const float* __restrict__ b_hh,  const float* __restrict__ W_out,
           const float* __restrict__ b_out, float* __restrict__ Y)
{
    // h double buffer, NATURAL layout: hbuf[buf][b][k] = h[k]; pad k=30..39 stays 0.
    __shared__ __align__(16) float hbuf[2][2][ROWF];

    const int lane = threadIdx.x;
    const int jp   = lane & 15;            // row-pair index; jp==15 is the Y-row (j0) + zero pad (j1)
    const int b    = lane >> 4;            // which of this warp's 2 batches
    const int j0   = 2 * jp, j1 = j0 + 1;
    const bool yrow = (jp == 15);
    const int batch = blockIdx.x * 2 + b;

    const float SC = 2.8853900817779268f;  // 2*log2(e), folded into pre-tanh weights

    // ---- weights packed over (k even, k odd): wa = row j0, wb = row j1 ----
    // jp<15:  wa,wb = SC*W_hh rows j0,j1 ; jp==15: wa = W_out (UNSCALED), wb = 0.
    ull wa[16], wb[16];
#pragma unroll
    for (int i = 0; i < 16; i++) {
        const int k0 = 2 * i, k1 = 2 * i + 1;
        float a0, a1;
        if (!yrow) {
            a0 = (k0 < HID) ? SC * W_hh[j0 * HID + k0] : 0.0f;
            a1 = (k1 < HID) ? SC * W_hh[j0 * HID + k1] : 0.0f;
        } else {
            a0 = (k0 < HID) ? W_out[k0] : 0.0f;
            a1 = (k1 < HID) ? W_out[k1] : 0.0f;
        }
        float c0 = (!yrow && k0 < HID) ? SC * W_hh[j1 * HID + k0] : 0.0f;
        float c1 = (!yrow && k1 < HID) ? SC * W_hh[j1 * HID + k1] : 0.0f;
        wa[i] = pk2(a0, a1);
        wb[i] = pk2(c0, c1);
    }
    const float wih0 = !yrow ? SC * W_ih[j0] : 0.0f;
    const float wih1 = !yrow ? SC * W_ih[j1] : 0.0f;
    const float bi0  = !yrow ? SC * (b_ih[j0] + b_hh[j0]) : b_out[0];
    const float bi1  = !yrow ? SC * (b_ih[j1] + b_hh[j1]) : 0.0f;

    // ---- zero both buffers incl. pad ----
#pragma unroll
    for (int i = lane; i < 2 * 2 * ROWF; i += 32)
        (&hbuf[0][0][0])[i] = 0.0f;
    __syncwarp();

    const float* Xb = X + batch;
    float*       Yb = Y + batch;

    // ---- X prefetch ring ----
    float xbuf[PF];
#pragma unroll
    for (int i = 0; i < PF; i++) xbuf[i] = Xb[i * BATCH];

    for (int s0 = 0; s0 < SEQ; s0 += PF) {
        const float* Xpf = Xb + (s0 + PF) * BATCH;
        const bool more = (s0 + PF) < SEQ;

#pragma unroll
        for (int u = 0; u < PF; u++) {
            const int s = s0 + u;
            const float4* hc = (const float4*)&hbuf[s & 1][b][0];
            float*        hn = &hbuf[(s & 1) ^ 1][b][0];

            // ---- consume x, refill PF steps ahead ----
            const float xc = xbuf[u];
            if (more) xbuf[u] = Xpf[u * BATCH];

            // ---- matvec: rows j0,j1, k-pair packing, 4 split chains.
            //      jp==15 row j0 computes y[s-1] = W_out·h + b_out for free. ----
            const float4 f0 = hc[0], f1 = hc[1], f2 = hc[2], f3 = hc[3];
            const float4 f4 = hc[4], f5 = hc[5], f6 = hc[6], f7 = hc[7];
            ull a0 = pk2(fmaf(wih0, xc, bi0), 0.0f), a1 = 0ull;
            ull c0 = pk2(fmaf(wih1, xc, bi1), 0.0f), c1 = 0ull;
            const ull h01 = pk2(f0.x, f0.y), h23 = pk2(f0.z, f0.w);
            const ull h45 = pk2(f1.x, f1.y), h67 = pk2(f1.z, f1.w);
            a0 = ffma2(wa[0], h01, a0);  a1 = ffma2(wa[1], h23, a1);
            c0 = ffma2(wb[0], h01, c0);  c1 = ffma2(wb[1], h23, c1);
            a0 = ffma2(wa[2], h45, a0);  a1 = ffma2(wa[3], h67, a1);
            c0 = ffma2(wb[2], h45, c0);  c1 = ffma2(wb[3], h67, c1);
            const ull h89 = pk2(f2.x, f2.y), hab = pk2(f2.z, f2.w);
            const ull hcd = pk2(f3.x, f3.y), hef = pk2(f3.z, f3.w);
            a0 = ffma2(wa[4], h89, a0);  a1 = ffma2(wa[5], hab, a1);
            c0 = ffma2(wb[4], h89, c0);  c1 = ffma2(wb[5], hab, c1);
            a0 = ffma2(wa[6], hcd, a0);  a1 = ffma2(wa[7], hef, a1);
            c0 = ffma2(wb[6], hcd, c0);  c1 = ffma2(wb[7], hef, c1);
            const ull hgh = pk2(f4.x, f4.y), hij = pk2(f4.z, f4.w);
            const ull hkl = pk2(f5.x, f5.y), hmn = pk2(f5.z, f5.w);
            a0 = ffma2(wa[8],  hgh, a0); a1 = ffma2(wa[9],  hij, a1);
            c0 = ffma2(wb[8],  hgh, c0); c1 = ffma2(wb[9],  hij, c1);
            a0 = ffma2(wa[10], hkl, a0); a1 = ffma2(wa[11], hmn, a1);
            c0 = ffma2(wb[10], hkl, c0); c1 = ffma2(wb[11], hmn, c1);
            const ull hop = pk2(f6.x, f6.y), hqr = pk2(f6.z, f6.w);
            const ull hst = pk2(f7.x, f7.y), huv = pk2(f7.z, f7.w);
            a0 = ffma2(wa[12], hop, a0); a1 = ffma2(wa[13], hqr, a1);
            c0 = ffma2(wb[12], hop, c0); c1 = ffma2(wb[13], hqr, c1);
            a0 = ffma2(wa[14], hst, a0); a1 = ffma2(wa[15], huv, a1);
            c0 = ffma2(wb[14], hst, c0); c1 = ffma2(wb[15], huv, c1);

            const ull sa = add2(a0, a1);
            const ull sc = add2(c0, c1);
            float sa0, sa1, sc0, sc1;
            unpk2(sa, sa0, sa1);
            unpk2(sc, sc0, sc1);
            const float v0 = sa0 + sa1;          // jp<15: pre-tanh unit j0 ; jp==15: y[s-1]
            const float v1 = sc0 + sc1;

            // ---- y store (lane 15 & 31, predicated — warp stays convergent) ----
            if (yrow && s > 0) Yb[(s - 1) * BATCH] = v0;

            // ---- tanh + publish h ----
            const float h0 = tanh_ps(v0);
            const float h1 = tanh_ps(v1);        // jp==15: v1==0 -> h1==0 exactly
            const float st0 = yrow ? 0.0f : h0;  // keep pad slot 30 at zero
            *(float2*)&hn[j0] = make_float2(st0, h1);

            // compiler barrier: keep next step's LDS after this STS (same-warp MIO is in-order)
            asm volatile("" ::: "memory");
        }
    }

    // ---- epilogue: y[SEQ-1] from final state (buffer 0, since SEQ is even) ----
    {
        const float4* hc = (const float4*)&hbuf[0][b][0];
        const float4 f0 = hc[0], f1 = hc[1], f2 = hc[2], f3 = hc[3];
        const float4 f4 = hc[4], f5 = hc[5], f6 = hc[6], f7 = hc[7];
        ull a0 = pk2(bi0, 0.0f), a1 = 0ull;
        a0 = ffma2(wa[0],  pk2(f0.x, f0.y), a0); a1 = ffma2(wa[1],  pk2(f0.z, f0.w), a1);
        a0 = ffma2(wa[2],  pk2(f1.x, f1.y), a0); a1 = ffma2(wa[3],  pk2(f1.z, f1.w), a1);
        a0 = ffma2(wa[4],  pk2(f2.x, f2.y), a0); a1 = ffma2(wa[5],  pk2(f2.z, f2.w), a1);
        a0 = ffma2(wa[6],  pk2(f3.x, f3.y), a0); a1 = ffma2(wa[7],  pk2(f3.z, f3.w), a1);
        a0 = ffma2(wa[8],  pk2(f4.x, f4.y), a0); a1 = ffma2(wa[9],  pk2(f4.z, f4.w), a1);
        a0 = ffma2(wa[10], pk2(f5.x, f5.y), a0); a1 = ffma2(wa[11], pk2(f5.z, f5.w), a1);
        a0 = ffma2(wa[12], pk2(f6.x, f6.y), a0); a1 = ffma2(wa[13], pk2(f6.z, f6.w), a1);
        a0 = ffma2(wa[14], pk2(f7.x, f7.y), a0); a1 = ffma2(wa[15], pk2(f7.z, f7.w), a1);
        const ull sa = add2(a0, a1);
        float sa0, sa1;
        unpk2(sa, sa0, sa1);
        if (yrow) Yb[(SEQ - 1) * BATCH] = sa0 + sa1;
    }
}

extern "C" void kernel_launch(void* const* d_in, const int* in_sizes, int n_in,
                              void* d_out, int out_size)
{
    (void)in_sizes; (void)n_in; (void)out_size;
    rnn_kernel<<<BATCH / 2, 32>>>(
        (const float*)d_in[0],  // X
        (const float*)d_in[1],  // W_ih
        (const float*)d_in[2],  // W_hh
        (const float*)d_in[3],  // b_ih
        (const float*)d_in[4],  // b_hh
        (const float*)d_in[5],  // W_out
        (const float*)d_in[6],  // b_out
        (float*)d_out);
}